// round 5
// baseline (speedup 1.0000x reference)
#include <cuda_runtime.h>
#include <cuda_bf16.h>

// Problem constants
#define NN   64
#define LL   1024
#define DD   512
#define LI_  1022
#define SS   127
#define OUTC 300
#define EPSF 1e-5f

// Scratch for span means (allocation-free rule: __device__ global)
__device__ float g_means[(size_t)NN * SS * DD];

// packed fp32x2 FMA (Blackwell FFMA2 — PTX only)
#define FMA_F32X2(d, a, b, c) \
    asm("fma.rn.f32x2 %0, %1, %2, %3;" : "=l"(d) : "l"(a), "l"(b), "l"(c))
#define UNPACK_F32X2(lo, hi, v) \
    asm("mov.b64 {%0, %1}, %2;" : "=f"(lo), "=f"(hi) : "l"(v))

// ---------------------------------------------------------------------------
// Kernel 1: span means + copy of `use = t1[:,0,:]`
// ---------------------------------------------------------------------------
__global__ void means_kernel(const float* __restrict__ t1,
                             const int* __restrict__ ws32,
                             float* __restrict__ out_use)
{
    int b = blockIdx.x;            // 0 .. NN*SS-1
    int n = b / SS;
    int s = b - n * SS;

    // word_seq dtype detection (int32 vs int64 storage).
    bool is64 = (ws32[1] == 0 && ws32[3] == 0);
    long long start, end;
    if (is64) {
        const long long* ws64 = (const long long*)ws32;
        start = ws64[(size_t)(n * SS + s) * 2];
        end   = ws64[(size_t)(n * SS + s) * 2 + 1];
    } else {
        start = ws32[(size_t)(n * SS + s) * 2];
        end   = ws32[(size_t)(n * SS + s) * 2 + 1];
    }
    if (start > (long long)(LI_ - 1)) start = LI_ - 1;
    if (end   > (long long)LI_)       end   = LI_;
    int cnt = (int)(end - start);

    int d4 = threadIdx.x;          // 0..127 -> float4 slot
    const float4* base =
        (const float4*)(t1 + ((size_t)n * LL + 1 + (size_t)start) * DD) + d4;

    float4 acc = make_float4(0.f, 0.f, 0.f, 0.f);
    if (cnt == 8) {
        float4 v[8];
#pragma unroll
        for (int r = 0; r < 8; ++r) v[r] = base[(size_t)r * (DD / 4)];
#pragma unroll
        for (int r = 0; r < 8; ++r) {
            acc.x += v[r].x; acc.y += v[r].y; acc.z += v[r].z; acc.w += v[r].w;
        }
    } else {
        for (int r = 0; r < cnt; ++r) {
            float4 v = base[(size_t)r * (DD / 4)];
            acc.x += v.x; acc.y += v.y; acc.z += v.z; acc.w += v.w;
        }
    }
    float inv = 1.0f / (float)cnt;
    acc.x *= inv; acc.y *= inv; acc.z *= inv; acc.w *= inv;
    ((float4*)(g_means + (size_t)b * DD))[d4] = acc;

    if (s == 0) {
        ((float4*)(out_use + (size_t)n * DD))[d4] =
            ((const float4*)(t1 + (size_t)n * LL * DD))[d4];
    }
}

// ---------------------------------------------------------------------------
// Kernel 2: GEMM h = means @ W^T + b, fused LayerNorm over OUT=300.
// 512 threads (16 warps -> 4 warps/SMSP), BM=64, BK=16, reg double-buffer.
// Warp w owns rows 4w..4w+3; thread micro-tile = 4 rows x 5 col-PAIRS.
// sA2[k][r] holds A duplicated {v,v} -> LDS.64, no packing.
// sB[k][c] column-contiguous -> float2 LDS.64 for col pairs.
// ---------------------------------------------------------------------------
#define BM 64
#define BK 16
#define NTILES (DD / BK)    // 32
#define SB_STRIDE 322       // even (8B-aligned f2) + conflict-free STS
#define SA_STRIDE 65        // conflict-free duplicated STS

__global__ __launch_bounds__(512, 1)
void gemm_ln_kernel(const float* __restrict__ W,      // [300,512] row-major
                    const float* __restrict__ blin,   // [300]
                    const float* __restrict__ gamma,  // [300]
                    const float* __restrict__ beta,   // [300]
                    float* __restrict__ out)          // [8128,300]
{
    __shared__ float2 sA2[2][BK][SA_STRIDE];   // ~16.6 KB
    __shared__ float  sB [2][BK][SB_STRIDE];   // ~41.2 KB

    int t    = threadIdx.x;
    int w    = t >> 5;       // warp 0..15
    int lane = t & 31;
    int rowBase = blockIdx.x * BM;

    const float* Ablk = g_means + (size_t)rowBase * DD;

    // zero-fill sB padding cols [300,322) once, both buffers
    for (int i = t; i < 2 * BK * (SB_STRIDE - OUTC); i += 512) {
        int buf = i / (BK * (SB_STRIDE - OUTC));
        int rem = i - buf * (BK * (SB_STRIDE - OUTC));
        int k = rem / (SB_STRIDE - OUTC);
        int c = OUTC + rem % (SB_STRIDE - OUTC);
        sB[buf][k][c] = 0.f;
    }

    unsigned long long acc2[4][5];
#pragma unroll
    for (int i = 0; i < 4; i++)
#pragma unroll
        for (int j = 0; j < 5; j++) acc2[i][j] = 0ull;

    // staging decomposition (fixed per thread)
    int rA0 = t >> 4,        kA = t & 15;          // A: i=0 -> r=rA0, i=1 -> r=rA0+32
    // B: lin = t + 512*i ; c = lin>>4, k = lin&15
    float rgA[2];
    float rgB[10];

    // prologue: tile 0 -> regs -> smem buf0
    {
        int kc = 0;
        rgA[0] = Ablk[(size_t)rA0 * DD + kc + kA];
        rgA[1] = Ablk[(size_t)(rA0 + 32) * DD + kc + kA];
#pragma unroll
        for (int i = 0; i < 10; i++) {
            int lin = t + 512 * i;
            int c = lin >> 4, k = lin & 15;
            if (c < OUTC) rgB[i] = W[(size_t)c * DD + kc + k];
        }
        sA2[0][kA][rA0]      = make_float2(rgA[0], rgA[0]);
        sA2[0][kA][rA0 + 32] = make_float2(rgA[1], rgA[1]);
#pragma unroll
        for (int i = 0; i < 10; i++) {
            int lin = t + 512 * i;
            int c = lin >> 4, k = lin & 15;
            if (c < OUTC) sB[0][k][c] = rgB[i];
        }
    }
    __syncthreads();

    int colBase = 2 * lane;      // thread's first column

    for (int tile = 0; tile < NTILES; ++tile) {
        int buf = tile & 1;

        // issue next-tile LDGs early (latency hidden by compute)
        if (tile + 1 < NTILES) {
            int kc = (tile + 1) * BK;
            rgA[0] = Ablk[(size_t)rA0 * DD + kc + kA];
            rgA[1] = Ablk[(size_t)(rA0 + 32) * DD + kc + kA];
#pragma unroll
            for (int i = 0; i < 10; i++) {
                int lin = t + 512 * i;
                int c = lin >> 4, k = lin & 15;
                if (c < OUTC) rgB[i] = W[(size_t)c * DD + kc + k];
            }
        }

        // compute
#pragma unroll
        for (int k = 0; k < BK; k++) {
            unsigned long long a2[4], b2[5];
#pragma unroll
            for (int i = 0; i < 4; i++)
                a2[i] = *reinterpret_cast<const unsigned long long*>(
                            &sA2[buf][k][4 * w + i]);        // broadcast LDS.64
#pragma unroll
            for (int j = 0; j < 5; j++)
                b2[j] = *reinterpret_cast<const unsigned long long*>(
                            &sB[buf][k][colBase + 64 * j]);  // cf-free LDS.64
#pragma unroll
            for (int i = 0; i < 4; i++)
#pragma unroll
                for (int j = 0; j < 5; j++)
                    FMA_F32X2(acc2[i][j], a2[i], b2[j], acc2[i][j]);
        }

        // store next tile into the other buffer
        if (tile + 1 < NTILES) {
            int nb = buf ^ 1;
            sA2[nb][kA][rA0]      = make_float2(rgA[0], rgA[0]);
            sA2[nb][kA][rA0 + 32] = make_float2(rgA[1], rgA[1]);
#pragma unroll
            for (int i = 0; i < 10; i++) {
                int lin = t + 512 * i;
                int c = lin >> 4, k = lin & 15;
                if (c < OUTC) sB[nb][k][c] = rgB[i];
            }
        }
        __syncthreads();
    }

    // epilogue: bias + per-row LayerNorm; thread holds 4 rows x 5 col-pairs
    const float2* blin2  = (const float2*)blin;
    const float2* gamma2 = (const float2*)gamma;
    const float2* beta2  = (const float2*)beta;

#pragma unroll
    for (int i = 0; i < 4; i++) {
        float ve[5], vo[5];
        float sum = 0.f, sq = 0.f;
#pragma unroll
        for (int j = 0; j < 5; j++) {
            int c0 = colBase + 64 * j;           // even; pair = (c0, c0+1)
            float lo, hi;
            UNPACK_F32X2(lo, hi, acc2[i][j]);
            if (c0 < OUTC) {
                float2 bb = blin2[c0 >> 1];
                lo += bb.x; hi += bb.y;
                ve[j] = lo; vo[j] = hi;
                sum += lo + hi;
                sq  += lo * lo + hi * hi;
            }
        }
#pragma unroll
        for (int off = 16; off; off >>= 1) {
            sum += __shfl_xor_sync(0xffffffffu, sum, off);
            sq  += __shfl_xor_sync(0xffffffffu, sq,  off);
        }
        float mu  = sum * (1.0f / OUTC);
        float inv = rsqrtf(sq * (1.0f / OUTC) - mu * mu + EPSF);

        int row = rowBase + 4 * w + i;
        float* o = out + (size_t)row * OUTC;
#pragma unroll
        for (int j = 0; j < 5; j++) {
            int c0 = colBase + 64 * j;
            if (c0 < OUTC) {
                float2 g = gamma2[c0 >> 1];
                float2 be = beta2[c0 >> 1];
                float2 r;
                r.x = (ve[j] - mu) * inv * g.x + be.x;
                r.y = (vo[j] - mu) * inv * g.y + be.y;
                *reinterpret_cast<float2*>(&o[c0]) = r;
            }
        }
    }
}

// ---------------------------------------------------------------------------
// Inputs (metadata order): t1, word_seq, key_padding_mask, w_lin, b_lin,
// gamma, beta.  Output: tuple (out[64,127,300], use[64,512]) concatenated.
// ---------------------------------------------------------------------------
extern "C" void kernel_launch(void* const* d_in, const int* in_sizes, int n_in,
                              void* d_out, int out_size)
{
    const float* t1    = (const float*)d_in[0];
    const int*   ws    = (const int*)  d_in[1];
    const float* W     = (const float*)d_in[3];
    const float* blin  = (const float*)d_in[4];
    const float* gamma = (const float*)d_in[5];
    const float* beta  = (const float*)d_in[6];

    float* out = (float*)d_out;
    float* use = out + (size_t)NN * SS * OUTC;

    means_kernel<<<NN * SS, 128>>>(t1, ws, use);
    gemm_ln_kernel<<<SS, 512>>>(W, blin, gamma, beta, out);
}

// round 6
// speedup vs baseline: 1.0133x; 1.0133x over previous
#include <cuda_runtime.h>
#include <cuda_bf16.h>

// Problem constants
#define NN   64
#define LL   1024
#define DD   512
#define LI_  1022
#define SS   127
#define OUTC 300
#define EPSF 1e-5f

__device__ float g_means[(size_t)NN * SS * DD];

// packed fp32x2 FMA (Blackwell FFMA2 — PTX only)
#define FMA_F32X2(d, a, b, c) \
    asm("fma.rn.f32x2 %0, %1, %2, %3;" : "=l"(d) : "l"(a), "l"(b), "l"(c))
#define PACK_DUP_F32X2(d, s) \
    asm("mov.b64 %0, {%1, %1};" : "=l"(d) : "r"(__float_as_uint(s)))
#define UNPACK_F32X2(lo, hi, v) \
    asm("mov.b64 {%0, %1}, %2;" : "=f"(lo), "=f"(hi) : "l"(v))

// ---------------------------------------------------------------------------
// Kernel 1: span means + copy of `use = t1[:,0,:]`
// ---------------------------------------------------------------------------
__global__ void means_kernel(const float* __restrict__ t1,
                             const int* __restrict__ ws32,
                             float* __restrict__ out_use)
{
    int b = blockIdx.x;
    int n = b / SS;
    int s = b - n * SS;

    bool is64 = (ws32[1] == 0 && ws32[3] == 0);
    long long start, end;
    if (is64) {
        const long long* ws64 = (const long long*)ws32;
        start = ws64[(size_t)(n * SS + s) * 2];
        end   = ws64[(size_t)(n * SS + s) * 2 + 1];
    } else {
        start = ws32[(size_t)(n * SS + s) * 2];
        end   = ws32[(size_t)(n * SS + s) * 2 + 1];
    }
    if (start > (long long)(LI_ - 1)) start = LI_ - 1;
    if (end   > (long long)LI_)       end   = LI_;
    int cnt = (int)(end - start);

    int d4 = threadIdx.x;
    const float4* base =
        (const float4*)(t1 + ((size_t)n * LL + 1 + (size_t)start) * DD) + d4;

    float4 acc = make_float4(0.f, 0.f, 0.f, 0.f);
    if (cnt == 8) {
        float4 v[8];
#pragma unroll
        for (int r = 0; r < 8; ++r) v[r] = base[(size_t)r * (DD / 4)];
#pragma unroll
        for (int r = 0; r < 8; ++r) {
            acc.x += v[r].x; acc.y += v[r].y; acc.z += v[r].z; acc.w += v[r].w;
        }
    } else {
        for (int r = 0; r < cnt; ++r) {
            float4 v = base[(size_t)r * (DD / 4)];
            acc.x += v.x; acc.y += v.y; acc.z += v.z; acc.w += v.w;
        }
    }
    float inv = 1.0f / (float)cnt;
    acc.x *= inv; acc.y *= inv; acc.z *= inv; acc.w *= inv;
    ((float4*)(g_means + (size_t)b * DD))[d4] = acc;

    if (s == 0) {
        ((float4*)(out_use + (size_t)n * DD))[d4] =
            ((const float4*)(t1 + (size_t)n * LL * DD))[d4];
    }
}

// ---------------------------------------------------------------------------
// Kernel 2: GEMM + fused LayerNorm.
// 512 threads (16 warps, 4/SMSP). Warp tile = 8 rows x 160 cols:
//   wr = w&7 -> rows 8wr..8wr+7 ; g = w>>3 -> cols [160g, 160g+160)
// Thread micro-tile: 4 row-PAIRS (f32x2 lanes) x 5 cols.
// A plain float layout sA[k][r] -> LDS.128 broadcast gives 2 row-pairs.
// B plain sB[k][c] -> dense LDS.32 + dup-mov.
// LayerNorm: intra-warp shfl + 2-way cross-warp smem combine.
// ---------------------------------------------------------------------------
#define BM 64
#define BK 16
#define NTILES (DD / BK)
#define SAS 68      // float stride per k: conflict-free STS, 16B-aligned rows
#define SBS 322     // float stride per k: conflict-free STS + dense LDS

__global__ __launch_bounds__(512, 1)
void gemm_ln_kernel(const float* __restrict__ W,
                    const float* __restrict__ blin,
                    const float* __restrict__ gamma,
                    const float* __restrict__ beta,
                    float* __restrict__ out)
{
    __shared__ float sA[2][BK][SAS];      // 8.5 KB
    __shared__ float sB[2][BK][SBS];      // 40.25 KB
    __shared__ float sRed[2][2][BM];      // [colgroup][sum|sq][row] 1 KB

    int t    = threadIdx.x;
    int w    = t >> 5;
    int lane = t & 31;
    int wr   = w & 7;        // row group (rows 8wr..8wr+7)
    int g    = w >> 3;       // col group (cols 160g..160g+159)
    int rowBase = blockIdx.x * BM;

    const float* Ablk = g_means + (size_t)rowBase * DD;

    // zero-fill sB pad cols [300,322), both buffers, once
    for (int i = t; i < 2 * BK * (SBS - OUTC); i += 512) {
        int buf = i / (BK * (SBS - OUTC));
        int rem = i - buf * (BK * (SBS - OUTC));
        int k = rem / (SBS - OUTC);
        int c = OUTC + rem % (SBS - OUTC);
        sB[buf][k][c] = 0.f;
    }

    unsigned long long acc2[4][5];
#pragma unroll
    for (int i = 0; i < 4; i++)
#pragma unroll
        for (int j = 0; j < 5; j++) acc2[i][j] = 0ull;

    // staging maps
    int rA = t & 63;             // A row
    int kA = t >> 6;             // A k: loads kA and kA+8
    float rgA[2];
    float rgB[10];

    // prologue: tile 0
    {
        rgA[0] = Ablk[(size_t)rA * DD + kA];
        rgA[1] = Ablk[(size_t)rA * DD + kA + 8];
#pragma unroll
        for (int i = 0; i < 10; i++) {
            int lin = t + 512 * i;
            int c = lin >> 4, k = lin & 15;
            if (c < OUTC) rgB[i] = W[(size_t)c * DD + k];
        }
        sA[0][kA][rA]     = rgA[0];
        sA[0][kA + 8][rA] = rgA[1];
#pragma unroll
        for (int i = 0; i < 10; i++) {
            int lin = t + 512 * i;
            int c = lin >> 4, k = lin & 15;
            if (c < OUTC) sB[0][k][c] = rgB[i];
        }
    }
    __syncthreads();

    int colBase = 160 * g + lane;    // thread col j -> colBase + 32j

    for (int tile = 0; tile < NTILES; ++tile) {
        int buf = tile & 1;

        if (tile + 1 < NTILES) {
            int kc = (tile + 1) * BK;
            rgA[0] = Ablk[(size_t)rA * DD + kc + kA];
            rgA[1] = Ablk[(size_t)rA * DD + kc + kA + 8];
#pragma unroll
            for (int i = 0; i < 10; i++) {
                int lin = t + 512 * i;
                int c = lin >> 4, k = lin & 15;
                if (c < OUTC) rgB[i] = W[(size_t)c * DD + kc + k];
            }
        }

#pragma unroll
        for (int k = 0; k < BK; k++) {
            unsigned long long a2[4], b2[5];
            // two LDS.128 broadcasts: rows 8wr..8wr+3 and 8wr+4..8wr+7
            ulonglong2 p0 = *reinterpret_cast<const ulonglong2*>(&sA[buf][k][8 * wr]);
            ulonglong2 p1 = *reinterpret_cast<const ulonglong2*>(&sA[buf][k][8 * wr + 4]);
            a2[0] = p0.x; a2[1] = p0.y; a2[2] = p1.x; a2[3] = p1.y;
#pragma unroll
            for (int j = 0; j < 5; j++) {
                float b = sB[buf][k][colBase + 32 * j];   // dense, cf-free
                PACK_DUP_F32X2(b2[j], b);
            }
#pragma unroll
            for (int i = 0; i < 4; i++)
#pragma unroll
                for (int j = 0; j < 5; j++)
                    FMA_F32X2(acc2[i][j], a2[i], b2[j], acc2[i][j]);
        }

        if (tile + 1 < NTILES) {
            int nb = buf ^ 1;
            sA[nb][kA][rA]     = rgA[0];
            sA[nb][kA + 8][rA] = rgA[1];
#pragma unroll
            for (int i = 0; i < 10; i++) {
                int lin = t + 512 * i;
                int c = lin >> 4, k = lin & 15;
                if (c < OUTC) sB[nb][k][c] = rgB[i];
            }
        }
        __syncthreads();
    }

    // ---------------- epilogue: bias + LayerNorm ----------------
    // v[r][j]: local row r (global row 8wr+r), col colBase+32j
    float v[8][5];
#pragma unroll
    for (int i = 0; i < 4; i++)
#pragma unroll
        for (int j = 0; j < 5; j++) {
            float lo, hi;
            UNPACK_F32X2(lo, hi, acc2[i][j]);
            int c = colBase + 32 * j;
            if (c < OUTC) {
                float bb = blin[c];
                v[2 * i][j]     = lo + bb;
                v[2 * i + 1][j] = hi + bb;
            } else {
                v[2 * i][j] = 0.f;
                v[2 * i + 1][j] = 0.f;
            }
        }

    // per-row warp-partial sums -> smem
#pragma unroll
    for (int r = 0; r < 8; r++) {
        float sum = 0.f, sq = 0.f;
#pragma unroll
        for (int j = 0; j < 5; j++) { sum += v[r][j]; sq += v[r][j] * v[r][j]; }
#pragma unroll
        for (int off = 16; off; off >>= 1) {
            sum += __shfl_xor_sync(0xffffffffu, sum, off);
            sq  += __shfl_xor_sync(0xffffffffu, sq,  off);
        }
        if (lane == 0) {
            sRed[g][0][8 * wr + r] = sum;
            sRed[g][1][8 * wr + r] = sq;
        }
    }
    __syncthreads();

#pragma unroll
    for (int r = 0; r < 8; r++) {
        int row = 8 * wr + r;
        float sum = sRed[0][0][row] + sRed[1][0][row];
        float sq  = sRed[0][1][row] + sRed[1][1][row];
        float mu  = sum * (1.0f / OUTC);
        float inv = rsqrtf(sq * (1.0f / OUTC) - mu * mu + EPSF);
        float* o = out + (size_t)(rowBase + row) * OUTC;
#pragma unroll
        for (int j = 0; j < 5; j++) {
            int c = colBase + 32 * j;
            if (c < OUTC)
                o[c] = (v[r][j] - mu) * inv * gamma[c] + beta[c];
        }
    }
}

// ---------------------------------------------------------------------------
extern "C" void kernel_launch(void* const* d_in, const int* in_sizes, int n_in,
                              void* d_out, int out_size)
{
    const float* t1    = (const float*)d_in[0];
    const int*   ws    = (const int*)  d_in[1];
    const float* W     = (const float*)d_in[3];
    const float* blin  = (const float*)d_in[4];
    const float* gamma = (const float*)d_in[5];
    const float* beta  = (const float*)d_in[6];

    float* out = (float*)d_out;
    float* use = out + (size_t)NN * SS * OUTC;

    means_kernel<<<NN * SS, 128>>>(t1, ws, use);
    gemm_ln_kernel<<<SS, 512>>>(W, blin, gamma, beta, out);
}

// round 8
// speedup vs baseline: 1.7377x; 1.7148x over previous
#include <cuda_runtime.h>
#include <cuda_bf16.h>
#include <cstdint>

// Problem constants
#define NN   64
#define LL   1024
#define DD   512
#define LI_  1022
#define SS   127
#define OUTC 300
#define EPSF 1e-5f

#define KTOT 1536          // 3 * 512 (split-bf16 concatenated K)
#define KCH  64            // K elements per SMEM stage (= 128B rows)
#define NSTG (KTOT / KCH)  // 24
#define MR   8128          // NN*SS

// Global scratch (allocation-free rule)
__device__ __align__(128) __nv_bfloat16 g_A[(size_t)MR * KTOT];
__device__ __align__(128) __nv_bfloat16 g_B[(size_t)320 * KTOT];

__device__ __forceinline__ uint32_t smem_u32(const void* p) {
    return (uint32_t)__cvta_generic_to_shared(p);
}
__device__ __forceinline__ void ldsm_x4(uint32_t addr, uint32_t& r0, uint32_t& r1,
                                        uint32_t& r2, uint32_t& r3) {
    asm volatile("ldmatrix.sync.aligned.m8n8.x4.shared.b16 {%0,%1,%2,%3}, [%4];"
                 : "=r"(r0), "=r"(r1), "=r"(r2), "=r"(r3) : "r"(addr));
}
__device__ __forceinline__ void mma16816(float* c, const uint32_t* a,
                                         uint32_t b0, uint32_t b1) {
    asm volatile("mma.sync.aligned.m16n8k16.row.col.f32.bf16.bf16.f32 "
                 "{%0,%1,%2,%3}, {%4,%5,%6,%7}, {%8,%9}, {%0,%1,%2,%3};"
                 : "+f"(c[0]), "+f"(c[1]), "+f"(c[2]), "+f"(c[3])
                 : "r"(a[0]), "r"(a[1]), "r"(a[2]), "r"(a[3]), "r"(b0), "r"(b1));
}

// ---------------------------------------------------------------------------
// Kernel 1: span means -> split-bf16 rows of g_A ([Ah|Al|Ah]) + `use` copy.
// grid = 8128, 128 threads.
// ---------------------------------------------------------------------------
__global__ void means_kernel(const float* __restrict__ t1,
                             const int* __restrict__ ws32,
                             float* __restrict__ out_use)
{
    int b  = blockIdx.x;
    int d4 = threadIdx.x;
    __nv_bfloat16* Arow = g_A + (size_t)b * KTOT;

    int n = b / SS;
    int s = b - n * SS;

    bool is64 = (ws32[1] == 0 && ws32[3] == 0);
    long long start, end;
    if (is64) {
        const long long* ws64 = (const long long*)ws32;
        start = ws64[(size_t)(n * SS + s) * 2];
        end   = ws64[(size_t)(n * SS + s) * 2 + 1];
    } else {
        start = ws32[(size_t)(n * SS + s) * 2];
        end   = ws32[(size_t)(n * SS + s) * 2 + 1];
    }
    if (start > (long long)(LI_ - 1)) start = LI_ - 1;
    if (end   > (long long)LI_)       end   = LI_;
    int cnt = (int)(end - start);

    const float4* base =
        (const float4*)(t1 + ((size_t)n * LL + 1 + (size_t)start) * DD) + d4;

    float4 acc = make_float4(0.f, 0.f, 0.f, 0.f);
    if (cnt == 8) {
        float4 v[8];
#pragma unroll
        for (int r = 0; r < 8; ++r) v[r] = base[(size_t)r * (DD / 4)];
#pragma unroll
        for (int r = 0; r < 8; ++r) {
            acc.x += v[r].x; acc.y += v[r].y; acc.z += v[r].z; acc.w += v[r].w;
        }
    } else {
        for (int r = 0; r < cnt; ++r) {
            float4 v = base[(size_t)r * (DD / 4)];
            acc.x += v.x; acc.y += v.y; acc.z += v.z; acc.w += v.w;
        }
    }
    float inv = 1.0f / (float)cnt;
    acc.x *= inv; acc.y *= inv; acc.z *= inv; acc.w *= inv;

    __nv_bfloat16 h0 = __float2bfloat16(acc.x), h1 = __float2bfloat16(acc.y);
    __nv_bfloat16 h2 = __float2bfloat16(acc.z), h3 = __float2bfloat16(acc.w);
    __nv_bfloat16 l0 = __float2bfloat16(acc.x - __bfloat162float(h0));
    __nv_bfloat16 l1 = __float2bfloat16(acc.y - __bfloat162float(h1));
    __nv_bfloat16 l2 = __float2bfloat16(acc.z - __bfloat162float(h2));
    __nv_bfloat16 l3 = __float2bfloat16(acc.w - __bfloat162float(h3));

    __nv_bfloat16 hbuf[4] = {h0, h1, h2, h3};
    __nv_bfloat16 lbuf[4] = {l0, l1, l2, l3};
    uint2 hp = *(uint2*)hbuf;
    uint2 lp = *(uint2*)lbuf;
    *(uint2*)(Arow + 4 * d4)        = hp;   // Ah
    *(uint2*)(Arow + 512 + 4 * d4)  = lp;   // Al
    *(uint2*)(Arow + 1024 + 4 * d4) = hp;   // Ah

    if (s == 0) {
        ((float4*)(out_use + (size_t)n * DD))[d4] =
            ((const float4*)(t1 + (size_t)n * LL * DD))[d4];
    }
}

// ---------------------------------------------------------------------------
// Kernel 2: split W[300][512] -> g_B[320][1536] = [Bh|Bh|Bl], rows>=300 zero.
// ---------------------------------------------------------------------------
__global__ void splitW_kernel(const float* __restrict__ W)
{
    int c  = blockIdx.x;
    int k4 = threadIdx.x * 4;
    __nv_bfloat16* Brow = g_B + (size_t)c * KTOT;

    if (c >= OUTC) {
        uint2 z = make_uint2(0u, 0u);
        *(uint2*)(Brow + k4)        = z;
        *(uint2*)(Brow + 512 + k4)  = z;
        *(uint2*)(Brow + 1024 + k4) = z;
        return;
    }
    float4 wv = *(const float4*)(W + (size_t)c * DD + k4);
    __nv_bfloat16 h0 = __float2bfloat16(wv.x), h1 = __float2bfloat16(wv.y);
    __nv_bfloat16 h2 = __float2bfloat16(wv.z), h3 = __float2bfloat16(wv.w);
    __nv_bfloat16 l0 = __float2bfloat16(wv.x - __bfloat162float(h0));
    __nv_bfloat16 l1 = __float2bfloat16(wv.y - __bfloat162float(h1));
    __nv_bfloat16 l2 = __float2bfloat16(wv.z - __bfloat162float(h2));
    __nv_bfloat16 l3 = __float2bfloat16(wv.w - __bfloat162float(h3));
    __nv_bfloat16 hbuf[4] = {h0, h1, h2, h3};
    __nv_bfloat16 lbuf[4] = {l0, l1, l2, l3};
    uint2 hp = *(uint2*)hbuf;
    uint2 lp = *(uint2*)lbuf;
    *(uint2*)(Brow + k4)        = hp;   // Bh
    *(uint2*)(Brow + 512 + k4)  = hp;   // Bh
    *(uint2*)(Brow + 1024 + k4) = lp;   // Bl
}

// ---------------------------------------------------------------------------
// Kernel 3: HMMA GEMM (mma.sync m16n8k16 bf16) + fused LayerNorm.
// grid = 127 CTAs (64 rows each), 256 threads (8 warps: 2 row x 4 col groups).
// Warp tile 32 rows x 80 cols = 2 m16-tiles x 10 n8-tiles; acc 80 f32 regs.
// K staged 64/chunk, SW128-swizzled smem + ldmatrix.x4, reg double-buffer.
// ---------------------------------------------------------------------------
#define A_STG 8192     // 64 rows * 128B
#define B_STG 40960    // 320 rows * 128B
#define DYN_SMEM (2 * (A_STG + B_STG))   // 98304

__global__ __launch_bounds__(256, 1)
void gemm_ln_kernel(const float* __restrict__ blin,
                    const float* __restrict__ gamma,
                    const float* __restrict__ beta,
                    float* __restrict__ out)
{
    extern __shared__ __align__(1024) char dyns[];
    __shared__ float sBias[320], sGamma[320], sBeta[320];
    __shared__ float sRed[4][2][64];
    __shared__ float sMu[64], sInv[64];

    int t    = threadIdx.x;
    int w    = t >> 5;
    int lane = t & 31;
    int wr   = w & 1;        // row group: rows 32*wr..32*wr+31
    int wc   = w >> 1;       // col group: cols 80*wc..80*wc+79
    int ctaRow = blockIdx.x * 64;

    for (int i = t; i < 320; i += 256) {
        sBias[i]  = (i < OUTC) ? blin[i]  : 0.f;
        sGamma[i] = (i < OUTC) ? gamma[i] : 0.f;
        sBeta[i]  = (i < OUTC) ? beta[i]  : 0.f;
    }

    float acc[2][10][4];
#pragma unroll
    for (int mi = 0; mi < 2; mi++)
#pragma unroll
        for (int ni = 0; ni < 10; ni++)
#pragma unroll
            for (int r = 0; r < 4; r++) acc[mi][ni][r] = 0.f;

    // ldmatrix per-thread constants
    int arow  = 32 * wr + (lane & 15);
    uint32_t aoff0 = (uint32_t)(arow * 128);
    uint32_t aoff1 = (uint32_t)((arow + 16) * 128);
    uint32_t axor  = (uint32_t)((arow & 7) << 4);
    uint32_t akl   = (uint32_t)(lane & 16);            // +16B for lanes>=16

    int brow_base = 80 * wc + (lane & 7) + ((lane >> 4) & 1) * 8;
    uint32_t bxor = (uint32_t)((lane & 7) << 4);
    uint32_t bkl  = (uint32_t)((lane & 8) * 2);        // +16B for lanes 8-15,24-31
    uint32_t boff[5];
#pragma unroll
    for (int tb = 0; tb < 5; tb++)
        boff[tb] = (uint32_t)((brow_base + 16 * tb) * 128);

    // staging maps (uint4 granularity; 8 uint4 per 128B row)
    // A: 512 uint4 -> 2/thread.  B: 2560 uint4 -> 10/thread.
    uint4 rgA[2], rgB[10];

    const uint4* gA = (const uint4*)(g_A + (size_t)ctaRow * KTOT);
    const uint4* gB = (const uint4*)g_B;
    // g_A row stride in uint4: 1536*2/16 = 192 ; g_B same.

    auto ldg_stage = [&](int s) {
#pragma unroll
        for (int i = 0; i < 2; i++) {
            int idx = t + 256 * i;
            int row = idx >> 3, q = idx & 7;
            rgA[i] = gA[(size_t)row * 192 + s * 8 + q];
        }
#pragma unroll
        for (int i = 0; i < 10; i++) {
            int idx = t + 256 * i;
            int row = idx >> 3, q = idx & 7;
            rgB[i] = gB[(size_t)row * 192 + s * 8 + q];
        }
    };
    auto sts_stage = [&](int buf) {
        char* a_s = dyns + buf * A_STG;
        char* b_s = dyns + 2 * A_STG + buf * B_STG;
#pragma unroll
        for (int i = 0; i < 2; i++) {
            int idx = t + 256 * i;
            int row = idx >> 3, q = idx & 7;
            uint32_t off = (uint32_t)(row * 128 + q * 16);
            *(uint4*)(a_s + (off ^ ((uint32_t)(row & 7) << 4))) = rgA[i];
        }
#pragma unroll
        for (int i = 0; i < 10; i++) {
            int idx = t + 256 * i;
            int row = idx >> 3, q = idx & 7;
            uint32_t off = (uint32_t)(row * 128 + q * 16);
            *(uint4*)(b_s + (off ^ ((uint32_t)(row & 7) << 4))) = rgB[i];
        }
    };

    // prologue
    ldg_stage(0);
    sts_stage(0);
    __syncthreads();

    for (int s = 0; s < NSTG; ++s) {
        int buf = s & 1;
        if (s + 1 < NSTG) ldg_stage(s + 1);

        uint32_t aBase = smem_u32(dyns + buf * A_STG);
        uint32_t bBase = smem_u32(dyns + 2 * A_STG + buf * B_STG);

#pragma unroll
        for (int ks = 0; ks < 4; ++ks) {
            uint32_t a[2][4];
            uint32_t kA = (uint32_t)(ks * 32) + akl;
            ldsm_x4(aBase + aoff0 + (kA ^ axor), a[0][0], a[0][1], a[0][2], a[0][3]);
            ldsm_x4(aBase + aoff1 + (kA ^ axor), a[1][0], a[1][1], a[1][2], a[1][3]);

            uint32_t kB = (uint32_t)(ks * 32) + bkl;
#pragma unroll
            for (int tb = 0; tb < 5; tb++) {
                uint32_t b0, b1, b2, b3;
                ldsm_x4(bBase + boff[tb] + (kB ^ bxor), b0, b1, b2, b3);
#pragma unroll
                for (int mi = 0; mi < 2; mi++) {
                    mma16816(acc[mi][2 * tb],     a[mi], b0, b1);
                    mma16816(acc[mi][2 * tb + 1], a[mi], b2, b3);
                }
            }
        }

        if (s + 1 < NSTG) sts_stage(buf ^ 1);
        __syncthreads();
    }

    // ---------------- epilogue: bias + LayerNorm ----------------
    int g = lane >> 2, q = lane & 3;

    float sum[4] = {0.f, 0.f, 0.f, 0.f};
    float sq[4]  = {0.f, 0.f, 0.f, 0.f};
#pragma unroll
    for (int mi = 0; mi < 2; mi++)
#pragma unroll
        for (int ni = 0; ni < 10; ni++) {
            int c0 = 80 * wc + 8 * ni + 2 * q;
            float b0 = sBias[c0], b1 = sBias[c0 + 1];
            float v0 = acc[mi][ni][0] + b0;
            float v1 = acc[mi][ni][1] + b1;
            float v2 = acc[mi][ni][2] + b0;
            float v3 = acc[mi][ni][3] + b1;
            acc[mi][ni][0] = v0; acc[mi][ni][1] = v1;
            acc[mi][ni][2] = v2; acc[mi][ni][3] = v3;
            sum[2 * mi]     += v0 + v1;  sq[2 * mi]     += v0 * v0 + v1 * v1;
            sum[2 * mi + 1] += v2 + v3;  sq[2 * mi + 1] += v2 * v2 + v3 * v3;
        }
#pragma unroll
    for (int off = 1; off <= 2; off <<= 1)
#pragma unroll
        for (int sl = 0; sl < 4; sl++) {
            sum[sl] += __shfl_xor_sync(0xffffffffu, sum[sl], off);
            sq[sl]  += __shfl_xor_sync(0xffffffffu, sq[sl],  off);
        }
    if (q == 0) {
#pragma unroll
        for (int sl = 0; sl < 4; sl++) {
            int lr = 32 * wr + 16 * (sl >> 1) + g + 8 * (sl & 1);
            sRed[wc][0][lr] = sum[sl];
            sRed[wc][1][lr] = sq[sl];
        }
    }
    __syncthreads();
    if (t < 64) {
        float S = sRed[0][0][t] + sRed[1][0][t] + sRed[2][0][t] + sRed[3][0][t];
        float Q = sRed[0][1][t] + sRed[1][1][t] + sRed[2][1][t] + sRed[3][1][t];
        float mu = S * (1.0f / OUTC);
        sMu[t]  = mu;
        sInv[t] = rsqrtf(Q * (1.0f / OUTC) - mu * mu + EPSF);
    }
    __syncthreads();

#pragma unroll
    for (int mi = 0; mi < 2; mi++) {
        int lr0 = 32 * wr + 16 * mi + g;       // rows for (v0,v1)
        int lr1 = lr0 + 8;                     // rows for (v2,v3)
        float mu0 = sMu[lr0], in0 = sInv[lr0];
        float mu1 = sMu[lr1], in1 = sInv[lr1];
        float* o0 = out + (size_t)(ctaRow + lr0) * OUTC;
        float* o1 = out + (size_t)(ctaRow + lr1) * OUTC;
#pragma unroll
        for (int ni = 0; ni < 10; ni++) {
            int c0 = 80 * wc + 8 * ni + 2 * q;
            if (c0 < OUTC) {
                float ga = sGamma[c0], gb = sGamma[c0 + 1];
                float ba = sBeta[c0],  bb = sBeta[c0 + 1];
                float2 r0, r1;
                r0.x = (acc[mi][ni][0] - mu0) * in0 * ga + ba;
                r0.y = (acc[mi][ni][1] - mu0) * in0 * gb + bb;
                r1.x = (acc[mi][ni][2] - mu1) * in1 * ga + ba;
                r1.y = (acc[mi][ni][3] - mu1) * in1 * gb + bb;
                *(float2*)(o0 + c0) = r0;
                *(float2*)(o1 + c0) = r1;
            }
        }
    }
}

// ---------------------------------------------------------------------------
extern "C" void kernel_launch(void* const* d_in, const int* in_sizes, int n_in,
                              void* d_out, int out_size)
{
    const float* t1    = (const float*)d_in[0];
    const int*   ws    = (const int*)  d_in[1];
    const float* W     = (const float*)d_in[3];
    const float* blin  = (const float*)d_in[4];
    const float* gamma = (const float*)d_in[5];
    const float* beta  = (const float*)d_in[6];

    float* out = (float*)d_out;
    float* use = out + (size_t)NN * SS * OUTC;

    cudaFuncSetAttribute(gemm_ln_kernel,
                         cudaFuncAttributeMaxDynamicSharedMemorySize, DYN_SMEM);

    splitW_kernel<<<320, 128>>>(W);
    means_kernel<<<MR, 128>>>(t1, ws, use);
    gemm_ln_kernel<<<SS, 256, DYN_SMEM>>>(blin, gamma, beta, out);
}

// round 9
// speedup vs baseline: 1.9535x; 1.1242x over previous
#include <cuda_runtime.h>
#include <cuda_bf16.h>
#include <cstdint>

// Problem constants
#define NN   64
#define LL   1024
#define DD   512
#define LI_  1022
#define SS   127
#define OUTC 300
#define EPSF 1e-5f

#define KSEG 512
#define KT2  1024          // dedup: [hi|lo]
#define KCH  64            // K elements per SMEM stage (= 128B rows)
#define NSTG 24            // 3 terms x 8 chunks
#define MR   8128          // NN*SS

// Global scratch (allocation-free rule)
__device__ __align__(128) __nv_bfloat16 g_A[(size_t)MR * KT2];   // [Ah|Al]
__device__ __align__(128) __nv_bfloat16 g_B[(size_t)320 * KT2];  // [Bh|Bl]

__device__ __forceinline__ uint32_t smem_u32(const void* p) {
    return (uint32_t)__cvta_generic_to_shared(p);
}
__device__ __forceinline__ void ldsm_x4(uint32_t addr, uint32_t& r0, uint32_t& r1,
                                        uint32_t& r2, uint32_t& r3) {
    asm volatile("ldmatrix.sync.aligned.m8n8.x4.shared.b16 {%0,%1,%2,%3}, [%4];"
                 : "=r"(r0), "=r"(r1), "=r"(r2), "=r"(r3) : "r"(addr));
}
__device__ __forceinline__ void mma16816(float* c, const uint32_t* a,
                                         uint32_t b0, uint32_t b1) {
    asm volatile("mma.sync.aligned.m16n8k16.row.col.f32.bf16.bf16.f32 "
                 "{%0,%1,%2,%3}, {%4,%5,%6,%7}, {%8,%9}, {%0,%1,%2,%3};"
                 : "+f"(c[0]), "+f"(c[1]), "+f"(c[2]), "+f"(c[3])
                 : "r"(a[0]), "r"(a[1]), "r"(a[2]), "r"(a[3]), "r"(b0), "r"(b1));
}
__device__ __forceinline__ void cp_async16(uint32_t dst, const void* src) {
    asm volatile("cp.async.cg.shared.global [%0], [%1], 16;" :: "r"(dst), "l"(src));
}
#define CP_COMMIT() asm volatile("cp.async.commit_group;")
#define CP_WAIT2()  asm volatile("cp.async.wait_group 2;" ::: "memory")

// ---------------------------------------------------------------------------
// Kernel 1: fused  (a) span means -> split-bf16 g_A rows [Ah|Al] + `use` copy
//                  (b) W split    -> g_B rows [Bh|Bl]
// grid = 8448: blocks [0,8128) = means, [8128,8448) = W rows. 128 threads.
// ---------------------------------------------------------------------------
__global__ void prep_kernel(const float* __restrict__ t1,
                            const int* __restrict__ ws32,
                            const float* __restrict__ W,
                            float* __restrict__ out_use)
{
    int b  = blockIdx.x;
    int d4 = threadIdx.x;

    if (b >= MR) {                       // ---- W split path ----
        int c  = b - MR;
        int k4 = d4 * 4;
        __nv_bfloat16* Brow = g_B + (size_t)c * KT2;
        if (c >= OUTC) {
            uint2 z = make_uint2(0u, 0u);
            *(uint2*)(Brow + k4)       = z;
            *(uint2*)(Brow + 512 + k4) = z;
            return;
        }
        float4 wv = *(const float4*)(W + (size_t)c * DD + k4);
        __nv_bfloat16 h0 = __float2bfloat16(wv.x), h1 = __float2bfloat16(wv.y);
        __nv_bfloat16 h2 = __float2bfloat16(wv.z), h3 = __float2bfloat16(wv.w);
        __nv_bfloat16 l0 = __float2bfloat16(wv.x - __bfloat162float(h0));
        __nv_bfloat16 l1 = __float2bfloat16(wv.y - __bfloat162float(h1));
        __nv_bfloat16 l2 = __float2bfloat16(wv.z - __bfloat162float(h2));
        __nv_bfloat16 l3 = __float2bfloat16(wv.w - __bfloat162float(h3));
        __nv_bfloat16 hbuf[4] = {h0, h1, h2, h3};
        __nv_bfloat16 lbuf[4] = {l0, l1, l2, l3};
        *(uint2*)(Brow + k4)       = *(uint2*)hbuf;
        *(uint2*)(Brow + 512 + k4) = *(uint2*)lbuf;
        return;
    }

    // ---- means path ----
    __nv_bfloat16* Arow = g_A + (size_t)b * KT2;
    int n = b / SS;
    int s = b - n * SS;

    bool is64 = (ws32[1] == 0 && ws32[3] == 0);
    long long start, end;
    if (is64) {
        const long long* ws64 = (const long long*)ws32;
        start = ws64[(size_t)(n * SS + s) * 2];
        end   = ws64[(size_t)(n * SS + s) * 2 + 1];
    } else {
        start = ws32[(size_t)(n * SS + s) * 2];
        end   = ws32[(size_t)(n * SS + s) * 2 + 1];
    }
    if (start > (long long)(LI_ - 1)) start = LI_ - 1;
    if (end   > (long long)LI_)       end   = LI_;
    int cnt = (int)(end - start);

    const float4* base =
        (const float4*)(t1 + ((size_t)n * LL + 1 + (size_t)start) * DD) + d4;

    float4 acc = make_float4(0.f, 0.f, 0.f, 0.f);
    if (cnt == 8) {
        float4 v[8];
#pragma unroll
        for (int r = 0; r < 8; ++r) v[r] = base[(size_t)r * (DD / 4)];
#pragma unroll
        for (int r = 0; r < 8; ++r) {
            acc.x += v[r].x; acc.y += v[r].y; acc.z += v[r].z; acc.w += v[r].w;
        }
    } else {
        for (int r = 0; r < cnt; ++r) {
            float4 v = base[(size_t)r * (DD / 4)];
            acc.x += v.x; acc.y += v.y; acc.z += v.z; acc.w += v.w;
        }
    }
    float inv = 1.0f / (float)cnt;
    acc.x *= inv; acc.y *= inv; acc.z *= inv; acc.w *= inv;

    __nv_bfloat16 h0 = __float2bfloat16(acc.x), h1 = __float2bfloat16(acc.y);
    __nv_bfloat16 h2 = __float2bfloat16(acc.z), h3 = __float2bfloat16(acc.w);
    __nv_bfloat16 l0 = __float2bfloat16(acc.x - __bfloat162float(h0));
    __nv_bfloat16 l1 = __float2bfloat16(acc.y - __bfloat162float(h1));
    __nv_bfloat16 l2 = __float2bfloat16(acc.z - __bfloat162float(h2));
    __nv_bfloat16 l3 = __float2bfloat16(acc.w - __bfloat162float(h3));
    __nv_bfloat16 hbuf[4] = {h0, h1, h2, h3};
    __nv_bfloat16 lbuf[4] = {l0, l1, l2, l3};
    *(uint2*)(Arow + 4 * d4)       = *(uint2*)hbuf;   // Ah
    *(uint2*)(Arow + 512 + 4 * d4) = *(uint2*)lbuf;   // Al

    if (s == 0) {
        ((float4*)(out_use + (size_t)n * DD))[d4] =
            ((const float4*)(t1 + (size_t)n * LL * DD))[d4];
    }
}

// ---------------------------------------------------------------------------
// Kernel 2: HMMA GEMM (mma.sync m16n8k16 bf16) + fused LayerNorm.
// grid = 127 CTAs (64 rows), 256 threads (8 warps: 2 row x 4 col groups).
// cp.async.cg 16B staging, 4-deep ring (192 KB), 1 barrier/stage.
// Stage s: term=s>>3 selects (A seg, B seg): (h,h) (l,h) (h,l); chunk=s&7.
// ---------------------------------------------------------------------------
#define A_STG 8192                  // 64 rows * 128B
#define B_STG 40960                 // 320 rows * 128B
#define STG_BYTES (A_STG + B_STG)   // 49152
#define DYN_SMEM (4 * STG_BYTES)    // 196608

__global__ __launch_bounds__(256, 1)
void gemm_ln_kernel(const float* __restrict__ blin,
                    const float* __restrict__ gamma,
                    const float* __restrict__ beta,
                    float* __restrict__ out)
{
    extern __shared__ __align__(1024) char dyns[];
    __shared__ float sBias[320], sGamma[320], sBeta[320];
    __shared__ float sRed[4][2][64];
    __shared__ float sMu[64], sInv[64];

    int t    = threadIdx.x;
    int w    = t >> 5;
    int lane = t & 31;
    int wr   = w & 1;        // row group: rows 32*wr..32*wr+31
    int wc   = w >> 1;       // col group: cols 80*wc..80*wc+79
    int ctaRow = blockIdx.x * 64;

    for (int i = t; i < 320; i += 256) {
        sBias[i]  = (i < OUTC) ? blin[i]  : 0.f;
        sGamma[i] = (i < OUTC) ? gamma[i] : 0.f;
        sBeta[i]  = (i < OUTC) ? beta[i]  : 0.f;
    }

    float acc[2][10][4];
#pragma unroll
    for (int mi = 0; mi < 2; mi++)
#pragma unroll
        for (int ni = 0; ni < 10; ni++)
#pragma unroll
            for (int r = 0; r < 4; r++) acc[mi][ni][r] = 0.f;

    // ldmatrix per-thread constants
    int arow  = 32 * wr + (lane & 15);
    uint32_t aoff0 = (uint32_t)(arow * 128);
    uint32_t aoff1 = (uint32_t)((arow + 16) * 128);
    uint32_t axor  = (uint32_t)((arow & 7) << 4);
    uint32_t akl   = (uint32_t)(lane & 16);

    int brow_base = 80 * wc + (lane & 7) + ((lane >> 4) & 1) * 8;
    uint32_t bxor = (uint32_t)((lane & 7) << 4);
    uint32_t bkl  = (uint32_t)((lane & 8) * 2);
    uint32_t boff[5];
#pragma unroll
    for (int tb = 0; tb < 5; tb++)
        boff[tb] = (uint32_t)((brow_base + 16 * tb) * 128);

    // staging maps: per thread per stage: A 2 x 16B, B 10 x 16B (cp.async)
    const uint4* gA = (const uint4*)(g_A + (size_t)ctaRow * KT2);   // row stride 128 uint4
    const uint4* gB = (const uint4*)g_B;

    // per-thread fixed staging coords
    int arow_s[2], aq_s[2];
#pragma unroll
    for (int i = 0; i < 2; i++) {
        int idx = t + 256 * i;
        arow_s[i] = idx >> 3; aq_s[i] = idx & 7;
    }
    int brow_s[10], bq_s[10];
#pragma unroll
    for (int i = 0; i < 10; i++) {
        int idx = t + 256 * i;
        brow_s[i] = idx >> 3; bq_s[i] = idx & 7;
    }

    auto issue_stage = [&](int s) {
        int term = s >> 3, c = s & 7;
        int aK4 = (term == 1 ? 64 : 0) + c * 8;   // uint4 offset within row
        int bK4 = (term == 2 ? 64 : 0) + c * 8;
        int buf = s & 3;
        uint32_t a_s = smem_u32(dyns + buf * STG_BYTES);
        uint32_t b_s = a_s + A_STG;
#pragma unroll
        for (int i = 0; i < 2; i++) {
            uint32_t off = (uint32_t)(arow_s[i] * 128 + aq_s[i] * 16);
            cp_async16(a_s + (off ^ ((uint32_t)(arow_s[i] & 7) << 4)),
                       gA + (size_t)arow_s[i] * 128 + aK4 + aq_s[i]);
        }
#pragma unroll
        for (int i = 0; i < 10; i++) {
            uint32_t off = (uint32_t)(brow_s[i] * 128 + bq_s[i] * 16);
            cp_async16(b_s + (off ^ ((uint32_t)(brow_s[i] & 7) << 4)),
                       gB + (size_t)brow_s[i] * 128 + bK4 + bq_s[i]);
        }
        CP_COMMIT();
    };

    // prologue: stages 0,1,2 in flight (3 groups)
    issue_stage(0);
    issue_stage(1);
    issue_stage(2);

    for (int s = 0; s < NSTG; ++s) {
        CP_WAIT2();              // stage s resident (pending <= 2)
        __syncthreads();         // all warps past compute(s-1); fill visible

        if (s + 3 < NSTG) issue_stage(s + 3);
        else              CP_COMMIT();      // keep group count telescoping

        int buf = s & 3;
        uint32_t aBase = smem_u32(dyns + buf * STG_BYTES);
        uint32_t bBase = aBase + A_STG;

#pragma unroll
        for (int ks = 0; ks < 4; ++ks) {
            uint32_t a[2][4];
            uint32_t kA = (uint32_t)(ks * 32) + akl;
            ldsm_x4(aBase + aoff0 + (kA ^ axor), a[0][0], a[0][1], a[0][2], a[0][3]);
            ldsm_x4(aBase + aoff1 + (kA ^ axor), a[1][0], a[1][1], a[1][2], a[1][3]);

            uint32_t kB = (uint32_t)(ks * 32) + bkl;
#pragma unroll
            for (int tb = 0; tb < 5; tb++) {
                uint32_t b0, b1, b2, b3;
                ldsm_x4(bBase + boff[tb] + (kB ^ bxor), b0, b1, b2, b3);
#pragma unroll
                for (int mi = 0; mi < 2; mi++) {
                    mma16816(acc[mi][2 * tb],     a[mi], b0, b1);
                    mma16816(acc[mi][2 * tb + 1], a[mi], b2, b3);
                }
            }
        }
    }

    // ---------------- epilogue: bias + LayerNorm ----------------
    int g = lane >> 2, q = lane & 3;

    float sum[4] = {0.f, 0.f, 0.f, 0.f};
    float sq[4]  = {0.f, 0.f, 0.f, 0.f};
#pragma unroll
    for (int mi = 0; mi < 2; mi++)
#pragma unroll
        for (int ni = 0; ni < 10; ni++) {
            int c0 = 80 * wc + 8 * ni + 2 * q;
            float b0 = sBias[c0], b1 = sBias[c0 + 1];
            float v0 = acc[mi][ni][0] + b0;
            float v1 = acc[mi][ni][1] + b1;
            float v2 = acc[mi][ni][2] + b0;
            float v3 = acc[mi][ni][3] + b1;
            acc[mi][ni][0] = v0; acc[mi][ni][1] = v1;
            acc[mi][ni][2] = v2; acc[mi][ni][3] = v3;
            sum[2 * mi]     += v0 + v1;  sq[2 * mi]     += v0 * v0 + v1 * v1;
            sum[2 * mi + 1] += v2 + v3;  sq[2 * mi + 1] += v2 * v2 + v3 * v3;
        }
#pragma unroll
    for (int off = 1; off <= 2; off <<= 1)
#pragma unroll
        for (int sl = 0; sl < 4; sl++) {
            sum[sl] += __shfl_xor_sync(0xffffffffu, sum[sl], off);
            sq[sl]  += __shfl_xor_sync(0xffffffffu, sq[sl],  off);
        }
    if (q == 0) {
#pragma unroll
        for (int sl = 0; sl < 4; sl++) {
            int lr = 32 * wr + 16 * (sl >> 1) + g + 8 * (sl & 1);
            sRed[wc][0][lr] = sum[sl];
            sRed[wc][1][lr] = sq[sl];
        }
    }
    __syncthreads();
    if (t < 64) {
        float S = sRed[0][0][t] + sRed[1][0][t] + sRed[2][0][t] + sRed[3][0][t];
        float Q = sRed[0][1][t] + sRed[1][1][t] + sRed[2][1][t] + sRed[3][1][t];
        float mu = S * (1.0f / OUTC);
        sMu[t]  = mu;
        sInv[t] = rsqrtf(Q * (1.0f / OUTC) - mu * mu + EPSF);
    }
    __syncthreads();

#pragma unroll
    for (int mi = 0; mi < 2; mi++) {
        int lr0 = 32 * wr + 16 * mi + g;
        int lr1 = lr0 + 8;
        float mu0 = sMu[lr0], in0 = sInv[lr0];
        float mu1 = sMu[lr1], in1 = sInv[lr1];
        float* o0 = out + (size_t)(ctaRow + lr0) * OUTC;
        float* o1 = out + (size_t)(ctaRow + lr1) * OUTC;
#pragma unroll
        for (int ni = 0; ni < 10; ni++) {
            int c0 = 80 * wc + 8 * ni + 2 * q;
            if (c0 < OUTC) {
                float ga = sGamma[c0], gb = sGamma[c0 + 1];
                float ba = sBeta[c0],  bb = sBeta[c0 + 1];
                float2 r0, r1;
                r0.x = (acc[mi][ni][0] - mu0) * in0 * ga + ba;
                r0.y = (acc[mi][ni][1] - mu0) * in0 * gb + bb;
                r1.x = (acc[mi][ni][2] - mu1) * in1 * ga + ba;
                r1.y = (acc[mi][ni][3] - mu1) * in1 * gb + bb;
                *(float2*)(o0 + c0) = r0;
                *(float2*)(o1 + c0) = r1;
            }
        }
    }
}

// ---------------------------------------------------------------------------
extern "C" void kernel_launch(void* const* d_in, const int* in_sizes, int n_in,
                              void* d_out, int out_size)
{
    const float* t1    = (const float*)d_in[0];
    const int*   ws    = (const int*)  d_in[1];
    const float* W     = (const float*)d_in[3];
    const float* blin  = (const float*)d_in[4];
    const float* gamma = (const float*)d_in[5];
    const float* beta  = (const float*)d_in[6];

    float* out = (float*)d_out;
    float* use = out + (size_t)NN * SS * OUTC;

    static bool attr_set = false;
    if (!attr_set) {
        cudaFuncSetAttribute(gemm_ln_kernel,
                             cudaFuncAttributeMaxDynamicSharedMemorySize, DYN_SMEM);
        attr_set = true;
    }

    prep_kernel<<<MR + 320, 128>>>(t1, ws, W, use);
    gemm_ln_kernel<<<SS, 256, DYN_SMEM>>>(blin, gamma, beta, out);
}